// round 6
// baseline (speedup 1.0000x reference)
#include <cuda_runtime.h>
#include <cuda_bf16.h>
#include <math.h>

#define NB   16
#define CH   64
#define HH   128
#define WW   128
#define PLANE (HH*WW)
#define GK2  72
#define BN_EPS 1e-5f

#define TROWS 32
#define HROWS (TROWS + 2)
#define TPI   (CH * 4)          // tiles per image = 256

__device__ float g_part[NB * CH * 4];   // per-tile partial sums
__device__ float g_f[NB * GK2];
__device__ int   g_cnt[NB];             // arrival counter (self-resetting)
__device__ int   g_cnt2[NB];            // departure counter (self-resetting)
__device__ int   g_flag[NB];            // weights-ready flag (self-resetting)

__device__ __forceinline__ void row_taps(float4 v, int lane, float wl, float wc, float wr,
                                         float acc[4]) {
    float left  = __shfl_up_sync(0xffffffffu, v.w, 1);
    float right = __shfl_down_sync(0xffffffffu, v.x, 1);
    if (lane == 0)  left  = v.y;
    if (lane == 31) right = v.z;
    acc[0] = fmaf(left, wl, fmaf(v.x, wc, fmaf(v.y, wr, acc[0])));
    acc[1] = fmaf(v.x,  wl, fmaf(v.y, wc, fmaf(v.z, wr, acc[1])));
    acc[2] = fmaf(v.y,  wl, fmaf(v.z, wc, fmaf(v.w, wr, acc[2])));
    acc[3] = fmaf(v.z,  wl, fmaf(v.w, wc, fmaf(right, wr, acc[3])));
}

__global__ void __launch_bounds__(256) fused_kernel(const float* __restrict__ x,
                                                    const float* __restrict__ conv_w,
                                                    const float* __restrict__ gamma,
                                                    const float* __restrict__ beta,
                                                    const float* __restrict__ mean,
                                                    const float* __restrict__ var,
                                                    float* __restrict__ out) {
    __shared__ float tile[HROWS * WW];           // 17408 B
    __shared__ float ws[8];
    __shared__ float sf[GK2];
    __shared__ float pooled_s[CH];
    __shared__ int   is_last;

    const int b = blockIdx.x;
    const int p = b >> 2;                        // plane = n*64 + c
    const int q = b & 3;                         // quadrant
    const int n = p >> 6;
    const int start = q * TROWS;
    const size_t base = (size_t)p * PLANE;
    const float4* xin = (const float4*)(x + base);
    float4* t4 = (float4*)tile;

    // ---- Phase 1: stage 34 rows (reflection baked in). Only DRAM read of x.
    #pragma unroll
    for (int j = 0; j < 5; j++) {
        const int i = threadIdx.x + j * 256;
        if (i < HROWS * 32) {
            int gr = start + (i >> 5) - 1;
            gr = (gr < 0) ? 1 : ((gr > HH - 1) ? HH - 2 : gr);
            t4[i] = xin[gr * 32 + (i & 31)];
        }
    }
    __syncthreads();

    // ---- Phase 2: partial sum of the 32 center rows, from smem.
    float s = 0.f;
    #pragma unroll
    for (int j = 0; j < 4; j++) {
        float4 v = t4[32 + threadIdx.x + j * 256];
        s += (v.x + v.y) + (v.z + v.w);
    }
    #pragma unroll
    for (int o = 16; o > 0; o >>= 1) s += __shfl_xor_sync(0xffffffffu, s, o);
    if ((threadIdx.x & 31) == 0) ws[threadIdx.x >> 5] = s;
    __syncthreads();
    if (threadIdx.x < 8) {
        s = ws[threadIdx.x];
        #pragma unroll
        for (int o = 4; o > 0; o >>= 1) s += __shfl_xor_sync(0x000000ffu, s, o);
        if (threadIdx.x == 0) {
            g_part[p * 4 + q] = s;
            __threadfence();
            int old = atomicAdd(&g_cnt[n], 1);
            is_last = (old == TPI - 1);
        }
    }
    __syncthreads();

    // ---- Phase 3: last tile of the image computes weights (deterministic).
    if (is_last) {
        __threadfence();                          // acquire all partials
        const int j = threadIdx.x;
        if (j < CH) {
            const float* pp = g_part + (n * CH + j) * 4;
            pooled_s[j] = ((pp[0] + pp[1]) + (pp[2] + pp[3])) * (1.f / (float)PLANE);
        }
        __syncthreads();
        if (j < GK2) {
            const float* wj = conv_w + j * CH;
            float acc = 0.f;
            #pragma unroll
            for (int c = 0; c < CH; c++) acc = fmaf(pooled_s[c], wj[c], acc);
            acc = gamma[j] * (acc - mean[j]) * rsqrtf(var[j] + BN_EPS) + beta[j];
            sf[j] = acc;
        }
        __syncthreads();
        if (j < GK2) {
            const int gg = j / 9;
            const float* sg = sf + gg * 9;
            float m = sg[0];
            #pragma unroll
            for (int i = 1; i < 9; i++) m = fmaxf(m, sg[i]);
            float sum = 0.f;
            #pragma unroll
            for (int i = 0; i < 9; i++) sum += __expf(sg[i] - m);
            g_f[n * GK2 + j] = __expf(sf[j] - m) / sum;
        }
        __syncthreads();
        if (j == 0) {
            __threadfence();                      // publish g_f before flag
            atomicExch(&g_flag[n], 1);
            g_cnt[n] = 0;                         // reset arrival counter
        }
    } else {
        // ---- spin until this image's weights are published
        if (threadIdx.x == 0) {
            while (atomicAdd(&g_flag[n], 0) == 0) __nanosleep(128);
        }
        __syncthreads();
        __threadfence();                          // acquire g_f
    }

    // ---- Phase 4: decouple from the already-staged smem tile.
    const int g = (p & 63) >> 3;
    const float* fw = g_f + n * GK2 + g * 9;
    float w[9];
    #pragma unroll
    for (int k = 0; k < 9; k++) w[k] = fw[k];

    float4* olow = (float4*)(out + base);
    float4* ores = (float4*)(out + (size_t)NB * CH * PLANE + base);
    const int lane = threadIdx.x & 31;
    const int warp = threadIdx.x >> 5;

    #pragma unroll
    for (int iter = 0; iter < TROWS / 8; iter++) {
        const int tr = iter * 8 + warp + 1;
        float4 va = t4[(tr - 1) * 32 + lane];
        float4 vb = t4[ tr      * 32 + lane];
        float4 vc = t4[(tr + 1) * 32 + lane];

        float acc[4] = {0.f, 0.f, 0.f, 0.f};
        row_taps(va, lane, w[0], w[1], w[2], acc);
        row_taps(vb, lane, w[3], w[4], w[5], acc);
        row_taps(vc, lane, w[6], w[7], w[8], acc);

        float4 L = make_float4(acc[0], acc[1], acc[2], acc[3]);
        float4 R = make_float4(vb.x - acc[0], vb.y - acc[1],
                               vb.z - acc[2], vb.w - acc[3]);
        const int oi = (start + tr - 1) * 32 + lane;
        __stcs(olow + oi, L);
        __stcs(ores + oi, R);
    }

    // ---- Phase 5: departure count; last leaver resets flag for graph replay.
    if (threadIdx.x == 0) {
        int old = atomicAdd(&g_cnt2[n], 1);
        if (old == TPI - 1) {
            g_flag[n] = 0;
            g_cnt2[n] = 0;
        }
    }
}

// ---------------------------------------------------------------------------
extern "C" void kernel_launch(void* const* d_in, const int* in_sizes, int n_in,
                              void* d_out, int out_size) {
    const float* x      = (const float*)d_in[0];
    const float* conv_w = (const float*)d_in[1];
    const float* gamma  = (const float*)d_in[2];
    const float* beta   = (const float*)d_in[3];
    const float* mean   = (const float*)d_in[4];
    const float* var    = (const float*)d_in[5];
    float* out = (float*)d_out;

    fused_kernel<<<NB * CH * 4, 256>>>(x, conv_w, gamma, beta, mean, var, out);
}

// round 8
// speedup vs baseline: 1.6793x; 1.6793x over previous
#include <cuda_runtime.h>
#include <cuda_bf16.h>
#include <math.h>

#define NB   16
#define CH   64
#define HH   128
#define WW   128
#define PLANE (HH*WW)          // 16384
#define GK2  72
#define BN_EPS 1e-5f

#define TROWS 32               // output rows per decouple CTA
#define HROWS (TROWS + 2)      // staged rows incl. halo

__device__ float g_pooled[NB * CH];
__device__ float g_f[NB * GK2];

// ---------------------------------------------------------------------------
// Kernel 1: adaptive avg pool. One CTA per plane; 16 float4 loads per thread.
// No fold, no fences — pure streaming read at the measured ceiling.
// ---------------------------------------------------------------------------
__global__ void __launch_bounds__(256) pool_kernel(const float* __restrict__ x) {
    const int p = blockIdx.x;
    const float4* xp = (const float4*)(x + (size_t)p * PLANE);
    float s = 0.f;
    #pragma unroll
    for (int j = 0; j < 16; j++) {
        float4 v = xp[threadIdx.x + j * 256];
        s += (v.x + v.y) + (v.z + v.w);
    }
    #pragma unroll
    for (int o = 16; o > 0; o >>= 1) s += __shfl_xor_sync(0xffffffffu, s, o);
    __shared__ float ws[8];
    if ((threadIdx.x & 31) == 0) ws[threadIdx.x >> 5] = s;
    __syncthreads();
    if (threadIdx.x < 8) {
        s = ws[threadIdx.x];
        #pragma unroll
        for (int o = 4; o > 0; o >>= 1) s += __shfl_xor_sync(0x000000ffu, s, o);
        if (threadIdx.x == 0) g_pooled[p] = s * (1.f / (float)PLANE);
    }
}

// ---------------------------------------------------------------------------
// Kernel 2: f = softmax_9( BN( pooled @ conv_w^T ) ).  16 x 72 threads.
// ---------------------------------------------------------------------------
__global__ void weights_kernel(const float* __restrict__ conv_w,
                               const float* __restrict__ gamma,
                               const float* __restrict__ beta,
                               const float* __restrict__ mean,
                               const float* __restrict__ var) {
    const int n = blockIdx.x;
    const int j = threadIdx.x;                    // 0..71
    const float* pn = g_pooled + n * CH;
    const float* wj = conv_w + j * CH;
    float acc = 0.f;
    #pragma unroll
    for (int c = 0; c < CH; c++) acc = fmaf(pn[c], wj[c], acc);
    acc = gamma[j] * (acc - mean[j]) * rsqrtf(var[j] + BN_EPS) + beta[j];

    __shared__ float s[GK2];
    s[j] = acc;
    __syncthreads();

    const int g = j / 9;
    const float* sg = s + g * 9;
    float m = sg[0];
    #pragma unroll
    for (int i = 1; i < 9; i++) m = fmaxf(m, sg[i]);
    float sum = 0.f;
    #pragma unroll
    for (int i = 0; i < 9; i++) sum += __expf(sg[i] - m);
    g_f[n * GK2 + j] = __expf(acc - m) / sum;
}

// ---------------------------------------------------------------------------
// Kernel 3: 32-row tiles + 34-row staged halo (reflection baked into staging).
// Warp-per-row, conflict-free LDS.128 + lane shuffles; __stcs float4 stores.
// Measured 30.7us standalone at 86% occupancy.
// ---------------------------------------------------------------------------
__device__ __forceinline__ void row_taps(float4 v, int lane, float wl, float wc, float wr,
                                         float acc[4]) {
    float left  = __shfl_up_sync(0xffffffffu, v.w, 1);
    float right = __shfl_down_sync(0xffffffffu, v.x, 1);
    if (lane == 0)  left  = v.y;   // reflect x[-1] -> x[1]
    if (lane == 31) right = v.z;   // reflect x[128] -> x[126]
    acc[0] = fmaf(left, wl, fmaf(v.x, wc, fmaf(v.y, wr, acc[0])));
    acc[1] = fmaf(v.x,  wl, fmaf(v.y, wc, fmaf(v.z, wr, acc[1])));
    acc[2] = fmaf(v.y,  wl, fmaf(v.z, wc, fmaf(v.w, wr, acc[2])));
    acc[3] = fmaf(v.z,  wl, fmaf(v.w, wc, fmaf(right, wr, acc[3])));
}

__global__ void __launch_bounds__(256) decouple_kernel(const float* __restrict__ x,
                                                       float* __restrict__ out) {
    __shared__ float tile[HROWS * WW];            // 17408 B
    const int b = blockIdx.x;
    const int p = b >> 2;                         // plane
    const int start = (b & 3) * TROWS;            // first output row
    const size_t base = (size_t)p * PLANE;
    const float4* xin = (const float4*)(x + base);
    float4* t4 = (float4*)tile;

    #pragma unroll
    for (int j = 0; j < (HROWS * 32 + 255) / 256; j++) {
        const int i = threadIdx.x + j * 256;
        if (i < HROWS * 32) {
            int gr = start + (i >> 5) - 1;
            gr = (gr < 0) ? 1 : ((gr > HH - 1) ? HH - 2 : gr);
            t4[i] = xin[gr * 32 + (i & 31)];
        }
    }

    const int n = p >> 6;
    const int g = (p & 63) >> 3;
    const float* fw = g_f + n * GK2 + g * 9;
    float w[9];
    #pragma unroll
    for (int k = 0; k < 9; k++) w[k] = fw[k];
    __syncthreads();

    float4* olow = (float4*)(out + base);
    float4* ores = (float4*)(out + (size_t)NB * CH * PLANE + base);

    const int lane = threadIdx.x & 31;
    const int warp = threadIdx.x >> 5;            // 0..7

    #pragma unroll
    for (int iter = 0; iter < TROWS / 8; iter++) {
        const int tr = iter * 8 + warp + 1;       // tile row (center)
        float4 va = t4[(tr - 1) * 32 + lane];
        float4 vb = t4[ tr      * 32 + lane];
        float4 vc = t4[(tr + 1) * 32 + lane];

        float acc[4] = {0.f, 0.f, 0.f, 0.f};
        row_taps(va, lane, w[0], w[1], w[2], acc);
        row_taps(vb, lane, w[3], w[4], w[5], acc);
        row_taps(vc, lane, w[6], w[7], w[8], acc);

        float4 L = make_float4(acc[0], acc[1], acc[2], acc[3]);
        float4 R = make_float4(vb.x - acc[0], vb.y - acc[1],
                               vb.z - acc[2], vb.w - acc[3]);
        const int oi = (start + tr - 1) * 32 + lane;
        __stcs(olow + oi, L);
        __stcs(ores + oi, R);
    }
}

// ---------------------------------------------------------------------------
extern "C" void kernel_launch(void* const* d_in, const int* in_sizes, int n_in,
                              void* d_out, int out_size) {
    const float* x      = (const float*)d_in[0];
    const float* conv_w = (const float*)d_in[1];
    const float* gamma  = (const float*)d_in[2];
    const float* beta   = (const float*)d_in[3];
    const float* mean   = (const float*)d_in[4];
    const float* var    = (const float*)d_in[5];
    float* out = (float*)d_out;

    pool_kernel<<<NB * CH, 256>>>(x);
    weights_kernel<<<NB, GK2>>>(conv_w, gamma, beta, mean, var);
    decouple_kernel<<<NB * CH * 4, 256>>>(x, out);
}